// round 1
// baseline (speedup 1.0000x reference)
#include <cuda_runtime.h>

#define H     20
#define SEQ   512
#define NB    4096

typedef unsigned long long u64;

__device__ __forceinline__ u64 pack2(float a, float b) {
    u64 r; asm("mov.b64 %0, {%1,%2};" : "=l"(r) : "f"(a), "f"(b)); return r;
}
__device__ __forceinline__ void unpack2(u64 v, float& a, float& b) {
    asm("mov.b64 {%0,%1}, %2;" : "=f"(a), "=f"(b) : "l"(v));
}
// Blackwell packed fp32 FMA (2x fp32 throughput vs scalar FFMA; PTX-only)
__device__ __forceinline__ u64 fma2(u64 a, u64 b, u64 c) {
    u64 d; asm("fma.rn.f32x2 %0, %1, %2, %3;" : "=l"(d) : "l"(a), "l"(b), "l"(c)); return d;
}
__device__ __forceinline__ u64 add2(u64 a, u64 b) {
    u64 d; asm("add.rn.f32x2 %0, %1, %2;" : "=l"(d) : "l"(a), "l"(b)); return d;
}
__device__ __forceinline__ float sigmoidf_(float v) {
    return __fdividef(1.0f, 1.0f + __expf(-v));
}
__device__ __forceinline__ float tanhf_(float v) {
    // tanh(v) = 2*sigmoid(2v) - 1; saturates correctly at +/-inf
    return fmaf(2.0f, __fdividef(1.0f, 1.0f + __expf(-2.0f * v)), -1.0f);
}

__global__ __launch_bounds__(128, 4) void lstm_fused(
    const float* __restrict__ x,     const float* __restrict__ W_ih,
    const float* __restrict__ W_hh,  const float* __restrict__ b_ih,
    const float* __restrict__ b_hh,  const float* __restrict__ W_lin,
    const float* __restrict__ b_lin, float* __restrict__ out)
{
    // Per-warp double-buffered h, stored duplicated {h,h} so LDS.128 yields
    // packed f32x2 multiplicands with no pack instructions.
    __shared__ __align__(16) float2 hbuf[4][2][H];

    const int warp = threadIdx.x >> 5;
    const int lane = threadIdx.x & 31;
    const int batch = blockIdx.x * 4 + warp;
    const int j = (lane < H) ? lane : (H - 1);   // clamp idle lanes to valid rows

    // Lane j owns hidden unit j: gate rows j (i), H+j (f), 2H+j (g), 3H+j (o).
    // Recurrent weights packed (i,f) and (g,o) -> 40 u64 = 80 regs.
    u64 wif[H], wgo[H];
#pragma unroll
    for (int k = 0; k < H; ++k) {
        wif[k] = pack2(W_hh[j * H + k],           W_hh[(H + j) * H + k]);
        wgo[k] = pack2(W_hh[(2 * H + j) * H + k], W_hh[(3 * H + j) * H + k]);
    }
    const u64 bif  = pack2(b_ih[j] + b_hh[j],             b_ih[H + j] + b_hh[H + j]);
    const u64 bgo  = pack2(b_ih[2 * H + j] + b_hh[2 * H + j],
                           b_ih[3 * H + j] + b_hh[3 * H + j]);
    const u64 wxif = pack2(W_ih[j],         W_ih[H + j]);
    const u64 wxgo = pack2(W_ih[2 * H + j], W_ih[3 * H + j]);
    const float wl = (lane < H) ? W_lin[lane] : 0.0f;  // idle lanes contribute 0
    const float bl = b_lin[0];

    if (lane < H) hbuf[warp][0][lane] = make_float2(0.0f, 0.0f);
    __syncwarp();

    float c = 0.0f;
    const float* xb = x + (size_t)batch * SEQ;
    float* ob = out + (size_t)batch * SEQ;

#pragma unroll 2
    for (int t = 0; t < SEQ; ++t) {
        const int rb = t & 1;
        const longlong2* hp = (const longlong2*)&hbuf[warp][rb][0];

        // x contribution is added at the END so the LDG latency hides behind
        // the 10-deep recurrent dot chains.
        float xt = __ldg(xb + t);
        u64 x2 = pack2(xt, xt);

        u64 aIF = bif, bIF = pack2(0.0f, 0.0f);
        u64 aGO = bgo, bGO = pack2(0.0f, 0.0f);
#pragma unroll
        for (int q = 0; q < H / 2; ++q) {
            longlong2 hh = hp[q];               // broadcast LDS.128: {h2k,h2k,h2k+1,h2k+1}
            u64 h0 = (u64)hh.x, h1 = (u64)hh.y;
            aIF = fma2(h0, wif[2 * q],     aIF);
            bIF = fma2(h1, wif[2 * q + 1], bIF);
            aGO = fma2(h0, wgo[2 * q],     aGO);
            bGO = fma2(h1, wgo[2 * q + 1], bGO);
        }
        u64 gIF = fma2(x2, wxif, add2(aIF, bIF));
        u64 gGO = fma2(x2, wxgo, add2(aGO, bGO));

        float gi, gf, gg, go;
        unpack2(gIF, gi, gf);
        unpack2(gGO, gg, go);
        float iv = sigmoidf_(gi);
        float fv = sigmoidf_(gf);
        float gv = tanhf_(gg);
        float ov = sigmoidf_(go);
        c = fmaf(fv, c, iv * gv);
        float h = ov * tanhf_(c);

        if (lane < H) hbuf[warp][rb ^ 1][lane] = make_float2(h, h);
        __syncwarp();

        // Linear head: out[b,t] = sum_j W_lin[j]*h_j + b_lin (butterfly reduce)
        float val = h * wl;
#pragma unroll
        for (int off = 16; off; off >>= 1)
            val += __shfl_xor_sync(0xffffffffu, val, off);
        if (lane == 0) ob[t] = val + bl;
    }
}

extern "C" void kernel_launch(void* const* d_in, const int* in_sizes, int n_in,
                              void* d_out, int out_size) {
    const float* x     = (const float*)d_in[0];
    const float* W_ih  = (const float*)d_in[1];
    const float* W_hh  = (const float*)d_in[2];
    const float* b_ih  = (const float*)d_in[3];
    const float* b_hh  = (const float*)d_in[4];
    const float* W_lin = (const float*)d_in[5];
    const float* b_lin = (const float*)d_in[6];
    float* out = (float*)d_out;

    lstm_fused<<<NB / 4, 128>>>(x, W_ih, W_hh, b_ih, b_hh, W_lin, b_lin, out);
}